// round 1
// baseline (speedup 1.0000x reference)
#include <cuda_runtime.h>
#include <math.h>

#define B_    512
#define S_    128
#define H_    768
#define DS_   384
#define NL_   40
#define H3_   2304
#define TEMP_INV_ 20.0f
#define ALPHA_    0.15f
#define GAMMA_    7.5f
#define EPS_      1e-8f

// ---------------- scratch (no allocations allowed) ----------------
__device__ float g_RH[B_ * H3_];        // tanh(concat(cls,head,tail))  512x2304
__device__ float g_TOKS[B_ * 4 * H_];   // raw gathered tokens          2048x768
__device__ float g_logits[B_ * NL_];    // 512x40
__device__ float g_rel[B_ * DS_];       // 512x384
__device__ float g_RN[B_ * DS_];        // l2n(rel_emb)
__device__ float g_DN[B_ * DS_];        // l2n(rel_desc_emb)
__device__ float g_D[B_ * 4 * H_];      // tanh(toks@dense_w+b)  2048x768
__device__ float g_Z1[B_ * 2 * H_];     // 512x1536 normalized
__device__ float g_Z2[B_ * 2 * H_];
__device__ float g_C[B_ * B_];          // 512x512
__device__ float g_cos[B_ * B_];        // 512x512
__device__ float g_ce[B_];
__device__ float g_m[B_];
__device__ float g_cl[B_];

// ---------------- gather + tanh prep ----------------
__global__ void gather_kernel(const float* __restrict__ bert,
                              const int* __restrict__ eidx,
                              float* __restrict__ RH,
                              float* __restrict__ TOKS)
{
    int b = blockIdx.x;
    const float* base0 = bert + (size_t)b * 2 * S_ * H_;   // seq 0
    const float* base1 = base0 + S_ * H_;                  // seq 1
    int i0 = eidx[b * 4 + 0];
    int i1 = eidx[b * 4 + 1];
    int i2 = eidx[b * 4 + 2];
    int i3 = eidx[b * 4 + 3];
    const float* cls = base0;
    const float* hd  = base0 + (size_t)i0 * H_;
    const float* tl  = base0 + (size_t)i1 * H_;
    const float* a2  = base1 + (size_t)i2 * H_;
    const float* b2  = base1 + (size_t)i3 * H_;
    float* rh = RH   + (size_t)b * H3_;
    float* tk = TOKS + (size_t)b * 4 * H_;
    for (int h = threadIdx.x; h < H_; h += blockDim.x) {
        float c = cls[h], hh = hd[h], tt = tl[h];
        rh[h]          = tanhf(c);
        rh[H_ + h]     = tanhf(hh);
        rh[2 * H_ + h] = tanhf(tt);
        tk[h]          = hh;
        tk[H_ + h]     = tt;
        tk[2 * H_ + h] = a2[h];
        tk[3 * H_ + h] = b2[h];
    }
}

// ---------------- generic tiled fp32 GEMM ----------------
// C[M,N] = epi( scale * A[M,K] @ B + bias )
// BT=false: B stored [K,N] row-major;  BT=true: B stored [N,K] row-major (B^T)
template<bool BT, bool TANH>
__global__ __launch_bounds__(256)
void gemm64(const float* __restrict__ A, const float* __restrict__ Bm,
            const float* __restrict__ bias, float* __restrict__ Cm,
            int M, int N, int K, float scale)
{
    const int BM = 64, BN = 64, BK = 16;
    __shared__ float As[BK][BM];
    __shared__ float Bs[BK][BN];
    int tid = threadIdx.x;
    int tx = tid & 15, ty = tid >> 4;
    int bm = blockIdx.y * BM, bn = blockIdx.x * BN;

    float acc[4][4];
#pragma unroll
    for (int i = 0; i < 4; i++)
#pragma unroll
        for (int j = 0; j < 4; j++) acc[i][j] = 0.f;

    int am = tid >> 2;            // 0..63
    int ak = (tid & 3) << 2;      // 0,4,8,12

    for (int k0 = 0; k0 < K; k0 += BK) {
        { // A tile
            float4 v = make_float4(0.f, 0.f, 0.f, 0.f);
            int gr = bm + am;
            if (gr < M) v = *reinterpret_cast<const float4*>(A + (size_t)gr * K + k0 + ak);
            As[ak + 0][am] = v.x; As[ak + 1][am] = v.y;
            As[ak + 2][am] = v.z; As[ak + 3][am] = v.w;
        }
        if (!BT) { // B [K,N]
            int kk = tid >> 4;            // 0..15
            int nl = (tid & 15) << 2;     // 0..60
            int gc = bn + nl;
            float4 v = make_float4(0.f, 0.f, 0.f, 0.f);
            if (gc + 3 < N) {
                v = *reinterpret_cast<const float4*>(Bm + (size_t)(k0 + kk) * N + gc);
            } else {
                float t0 = (gc + 0 < N) ? Bm[(size_t)(k0 + kk) * N + gc + 0] : 0.f;
                float t1 = (gc + 1 < N) ? Bm[(size_t)(k0 + kk) * N + gc + 1] : 0.f;
                float t2 = (gc + 2 < N) ? Bm[(size_t)(k0 + kk) * N + gc + 2] : 0.f;
                float t3 = (gc + 3 < N) ? Bm[(size_t)(k0 + kk) * N + gc + 3] : 0.f;
                v = make_float4(t0, t1, t2, t3);
            }
            Bs[kk][nl + 0] = v.x; Bs[kk][nl + 1] = v.y;
            Bs[kk][nl + 2] = v.z; Bs[kk][nl + 3] = v.w;
        } else {   // B^T stored [N,K]
            int nl = tid >> 2;            // 0..63
            int kk = (tid & 3) << 2;      // 0,4,8,12
            int gr = bn + nl;
            float4 v = make_float4(0.f, 0.f, 0.f, 0.f);
            if (gr < N) v = *reinterpret_cast<const float4*>(Bm + (size_t)gr * K + k0 + kk);
            Bs[kk + 0][nl] = v.x; Bs[kk + 1][nl] = v.y;
            Bs[kk + 2][nl] = v.z; Bs[kk + 3][nl] = v.w;
        }
        __syncthreads();

#pragma unroll
        for (int kk = 0; kk < BK; kk++) {
            float a[4], bfrag[4];
#pragma unroll
            for (int i = 0; i < 4; i++) a[i] = As[kk][ty * 4 + i];
#pragma unroll
            for (int j = 0; j < 4; j++) bfrag[j] = Bs[kk][tx * 4 + j];
#pragma unroll
            for (int i = 0; i < 4; i++)
#pragma unroll
                for (int j = 0; j < 4; j++)
                    acc[i][j] = fmaf(a[i], bfrag[j], acc[i][j]);
        }
        __syncthreads();
    }

#pragma unroll
    for (int i = 0; i < 4; i++) {
        int r = bm + ty * 4 + i;
        if (r >= M) continue;
#pragma unroll
        for (int j = 0; j < 4; j++) {
            int c = bn + tx * 4 + j;
            if (c >= N) continue;
            float v = acc[i][j] * scale + (bias ? bias[c] : 0.f);
            if (TANH) v = tanhf(v);
            Cm[(size_t)r * N + c] = v;
        }
    }
}

// ---------------- row L2 normalize (deterministic block reduce) ----------------
__global__ void l2norm_kernel(const float* __restrict__ X, float* __restrict__ Y,
                              int K, int strideX)
{
    int b = blockIdx.x;
    int tid = threadIdx.x;
    const float* x = X + (size_t)b * strideX;
    float* y = Y + (size_t)b * K;
    float s = 0.f;
    for (int i = tid; i < K; i += blockDim.x) { float v = x[i]; s += v * v; }
    __shared__ float red[256];
    red[tid] = s; __syncthreads();
    for (int st = 128; st > 0; st >>= 1) {
        if (tid < st) red[tid] += red[tid + st];
        __syncthreads();
    }
    float inv = 1.f / fmaxf(sqrtf(red[0]), EPS_);
    for (int i = tid; i < K; i += blockDim.x) y[i] = x[i] * inv;
}

// ---------------- per-row CE on logits (40 classes) ----------------
__global__ void ce_kernel(const float* __restrict__ logits,
                          const int* __restrict__ lab,
                          float* __restrict__ ce)
{
    int b = blockIdx.x * blockDim.x + threadIdx.x;
    if (b >= B_) return;
    const float* row = logits + (size_t)b * NL_;
    float mx = -INFINITY;
    for (int j = 0; j < NL_; j++) mx = fmaxf(mx, row[j]);
    float s = 0.f;
    for (int j = 0; j < NL_; j++) s += expf(row[j] - mx);
    ce[b] = mx + logf(s) - row[lab[b]];
}

// ---------------- per-row margin on C ----------------
__global__ void margin_kernel(const float* __restrict__ Cm,
                              const int* __restrict__ lab,
                              float* __restrict__ mout)
{
    int b = blockIdx.x, tid = threadIdx.x;
    int lb = lab[b];
    const float* row = Cm + (size_t)b * B_;
    float mx = -INFINITY;
    for (int j = tid; j < B_; j += blockDim.x)
        if (lab[j] != lb) mx = fmaxf(mx, row[j]);
    __shared__ float red[256];
    red[tid] = mx; __syncthreads();
    for (int st = 128; st > 0; st >>= 1) {
        if (tid < st) red[tid] = fmaxf(red[tid], red[tid + st]);
        __syncthreads();
    }
    if (tid == 0) {
        float neg = fmaxf(red[0], 0.f);
        float pos = row[b];
        mout[b] = fmaxf(neg - pos + GAMMA_, 0.f) * (1.0f - ALPHA_);
    }
}

// ---------------- per-row CE on cos_sim (diag labels) ----------------
__global__ void cl_kernel(const float* __restrict__ cosm, float* __restrict__ cl)
{
    int b = blockIdx.x, tid = threadIdx.x;
    const float* row = cosm + (size_t)b * B_;
    float mx = -INFINITY;
    for (int j = tid; j < B_; j += blockDim.x) mx = fmaxf(mx, row[j]);
    __shared__ float red[256];
    red[tid] = mx; __syncthreads();
    for (int st = 128; st > 0; st >>= 1) {
        if (tid < st) red[tid] = fmaxf(red[tid], red[tid + st]);
        __syncthreads();
    }
    float m = red[0];
    __syncthreads();
    float s = 0.f;
    for (int j = tid; j < B_; j += blockDim.x) s += expf(row[j] - m);
    red[tid] = s; __syncthreads();
    for (int st = 128; st > 0; st >>= 1) {
        if (tid < st) red[tid] += red[tid + st];
        __syncthreads();
    }
    if (tid == 0) cl[b] = m + logf(red[0]) - row[b];
}

// ---------------- final combine ----------------
__global__ void final_kernel(const float* __restrict__ ce,
                             const float* __restrict__ m,
                             const float* __restrict__ cl,
                             float* __restrict__ out)
{
    int tid = threadIdx.x;
    float v = ce[tid] * (1.0f / B_) + m[tid] + (ALPHA_ / B_) * cl[tid];
    __shared__ float red[512];
    red[tid] = v; __syncthreads();
    for (int st = 256; st > 0; st >>= 1) {
        if (tid < st) red[tid] += red[tid + st];
        __syncthreads();
    }
    if (tid == 0) out[0] = red[0];
}

// ---------------- host launcher ----------------
extern "C" void kernel_launch(void* const* d_in, const int* in_sizes, int n_in,
                              void* d_out, int out_size)
{
    const float* bert    = (const float*)d_in[0];
    const float* rdesc   = (const float*)d_in[1];
    const float* dense_w = (const float*)d_in[2];
    const float* dense_b = (const float*)d_in[3];
    const float* cls_w   = (const float*)d_in[4];
    const float* cls_b   = (const float*)d_in[5];
    const float* fc_w    = (const float*)d_in[6];
    const float* fc_b    = (const float*)d_in[7];
    const int*   eidx    = (const int*)d_in[8];
    const int*   lab     = (const int*)d_in[9];
    float* out = (float*)d_out;

    float *RH, *TOKS, *logits, *rel, *RN, *DN, *D, *Z1, *Z2, *Cm, *cosm, *ce, *mm, *cl;
    cudaGetSymbolAddress((void**)&RH,     g_RH);
    cudaGetSymbolAddress((void**)&TOKS,   g_TOKS);
    cudaGetSymbolAddress((void**)&logits, g_logits);
    cudaGetSymbolAddress((void**)&rel,    g_rel);
    cudaGetSymbolAddress((void**)&RN,     g_RN);
    cudaGetSymbolAddress((void**)&DN,     g_DN);
    cudaGetSymbolAddress((void**)&D,      g_D);
    cudaGetSymbolAddress((void**)&Z1,     g_Z1);
    cudaGetSymbolAddress((void**)&Z2,     g_Z2);
    cudaGetSymbolAddress((void**)&Cm,     g_C);
    cudaGetSymbolAddress((void**)&cosm,   g_cos);
    cudaGetSymbolAddress((void**)&ce,     g_ce);
    cudaGetSymbolAddress((void**)&mm,     g_m);
    cudaGetSymbolAddress((void**)&cl,     g_cl);

    // 1. gathers + tanh prep
    gather_kernel<<<B_, 256>>>(bert, eidx, RH, TOKS);

    // 2. GEMMs
    gemm64<false, false><<<dim3( 1,  8), 256>>>(RH,   cls_w,   cls_b,   logits, B_,   NL_, H3_, 1.f);
    gemm64<false, false><<<dim3( 6,  8), 256>>>(RH,   fc_w,    fc_b,    rel,    B_,   DS_, H3_, 1.f);
    gemm64<false, true ><<<dim3(12, 32), 256>>>(TOKS, dense_w, dense_b, D,      4*B_, H_,  H_,  1.f);

    // 3. normalizations
    l2norm_kernel<<<B_, 256>>>(rel,      RN, DS_,   DS_);
    l2norm_kernel<<<B_, 256>>>(rdesc,    DN, DS_,   DS_);
    l2norm_kernel<<<B_, 256>>>(D,        Z1, 2*H_,  4*H_);   // rows 4b,4b+1
    l2norm_kernel<<<B_, 256>>>(D + 2*H_, Z2, 2*H_,  4*H_);   // rows 4b+2,4b+3

    // 4. similarity GEMMs (NT)
    gemm64<true, false><<<dim3(8, 8), 256>>>(RN, DN, nullptr, Cm,   B_, B_, DS_,  1.f);
    gemm64<true, false><<<dim3(8, 8), 256>>>(Z1, Z2, nullptr, cosm, B_, B_, 2*H_, TEMP_INV_);

    // 5. losses (deterministic, no atomics)
    ce_kernel<<<2, 256>>>(logits, lab, ce);
    margin_kernel<<<B_, 256>>>(Cm, lab, mm);
    cl_kernel<<<B_, 256>>>(cosm, cl);
    final_kernel<<<1, 512>>>(ce, mm, cl, out);
}

// round 2
// speedup vs baseline: 1.7167x; 1.7167x over previous
#include <cuda_runtime.h>
#include <math.h>

#define B_    512
#define S_    128
#define H_    768
#define DS_   384
#define NL_   40
#define H3_   2304
#define NP_   424          // packed N = 40 + 384
#define TEMP_INV_ 20.0f
#define ALPHA_    0.15f
#define GAMMA_    7.5f
#define EPS_      1e-8f

// ---------------- scratch ----------------
__device__ float g_RH[B_ * H3_];          // tanh(concat) 512x2304
__device__ float g_TOKS[B_ * 4 * H_];     // 2048x768
__device__ float g_W[H3_ * NP_];          // packed [2304,424]
__device__ float g_biasP[NP_];
__device__ float g_P1[6 * B_ * NP_];      // split-K partials packed gemm
__device__ float g_LR[B_ * NP_];          // logits(0..39) | rel(40..423)
__device__ float g_D[B_ * 4 * H_];        // tanh(toks@dense_w+b) 2048x768
__device__ float g_P2[2 * B_ * B_];       // C partials
__device__ float g_P3[4 * B_ * B_];       // cos partials
__device__ float g_C[B_ * B_];
__device__ float g_cos[B_ * B_];
__device__ float g_norms[4 * B_];         // recip norms: rel, rdesc, z1, z2
__device__ float g_ce[B_];
__device__ float g_m[B_];
__device__ float g_cl[B_];

// ---------------- gather + tanh (float4) ----------------
__global__ void gather_kernel(const float* __restrict__ bert,
                              const int* __restrict__ eidx,
                              float* __restrict__ RH,
                              float* __restrict__ TOKS)
{
    int b = blockIdx.x, t = threadIdx.x;        // t in 0..191 (768/4)
    const float* base0 = bert + (size_t)b * 2 * S_ * H_;
    const float* base1 = base0 + S_ * H_;
    int i0 = eidx[b*4+0], i1 = eidx[b*4+1], i2 = eidx[b*4+2], i3 = eidx[b*4+3];
    float4 c  = ((const float4*)base0)[t];
    float4 hh = ((const float4*)(base0 + (size_t)i0*H_))[t];
    float4 tl = ((const float4*)(base0 + (size_t)i1*H_))[t];
    float4 a2 = ((const float4*)(base1 + (size_t)i2*H_))[t];
    float4 b2 = ((const float4*)(base1 + (size_t)i3*H_))[t];
    float4* rh = (float4*)(RH + (size_t)b*H3_);
    float4* tk = (float4*)(TOKS + (size_t)b*4*H_);
    float4 tc = make_float4(tanhf(c.x),tanhf(c.y),tanhf(c.z),tanhf(c.w));
    float4 th = make_float4(tanhf(hh.x),tanhf(hh.y),tanhf(hh.z),tanhf(hh.w));
    float4 tt = make_float4(tanhf(tl.x),tanhf(tl.y),tanhf(tl.z),tanhf(tl.w));
    rh[t] = tc; rh[192+t] = th; rh[384+t] = tt;
    tk[t] = hh; tk[192+t] = tl; tk[384+t] = a2; tk[576+t] = b2;
}

// ---------------- pack weights ----------------
__global__ void pack_kernel(const float* __restrict__ cls_w, const float* __restrict__ fc_w,
                            const float* __restrict__ cls_b, const float* __restrict__ fc_b,
                            float* __restrict__ W, float* __restrict__ biasP)
{
    int idx = blockIdx.x*blockDim.x + threadIdx.x;
    const int total = H3_ * NP_;
    for (int i = idx; i < total; i += gridDim.x*blockDim.x) {
        int k = i / NP_, c = i % NP_;
        W[i] = (c < NL_) ? cls_w[(size_t)k*NL_ + c] : fc_w[(size_t)k*DS_ + (c-NL_)];
    }
    if (idx < NP_) biasP[idx] = (idx < NL_) ? cls_b[idx] : fc_b[idx-NL_];
}

// ---------------- 128x64 tile GEMM, 8x8/thread, optional NT / tanh / split-K ----------------
template<bool NT, bool TANH, bool SPLIT>
__global__ __launch_bounds__(128)
void gemm_k(const float* __restrict__ A, const float* __restrict__ B,
            const float* __restrict__ bias, float* __restrict__ C,
            int M, int N, int K, int lda, int ldb, int ldc, int kChunk, float scale)
{
    __shared__ float As[16][132];
    __shared__ float Bs[16][68];
    int tid = threadIdx.x;
    int bm = blockIdx.y * 128, bn = blockIdx.x * 64;
    int tx = tid & 7, ty = tid >> 3;

    float acc[8][8];
#pragma unroll
    for (int i=0;i<8;i++)
#pragma unroll
        for (int j=0;j<8;j++) acc[i][j]=0.f;

    int kBeg = SPLIT ? blockIdx.z * kChunk : 0;
    int kEnd = SPLIT ? min(K, kBeg + kChunk) : K;

    int arow = bm + tid;
    bool aval = arow < M;
    int nrow = tid >> 1;
    int j0 = (tid & 1) * 8;
    bool nval = (bn + nrow) < N;

    for (int k0 = kBeg; k0 < kEnd; k0 += 16) {
        // A tile: one row per thread, 16 K-cols
#pragma unroll
        for (int j = 0; j < 4; j++) {
            float4 v = make_float4(0.f,0.f,0.f,0.f);
            if (aval) v = *(const float4*)(A + (size_t)arow*lda + k0 + j*4);
            As[j*4+0][tid]=v.x; As[j*4+1][tid]=v.y; As[j*4+2][tid]=v.z; As[j*4+3][tid]=v.w;
        }
        if (!NT) {
#pragma unroll
            for (int i = 0; i < 2; i++) {
                int f = tid*2 + i;
                int r = f >> 4;
                int c4 = (f & 15) * 4;
                int gc = bn + c4;
                float4 v;
                if (gc + 3 < N) v = *(const float4*)(B + (size_t)(k0+r)*ldb + gc);
                else {
                    v.x = (gc+0<N)? B[(size_t)(k0+r)*ldb+gc+0] : 0.f;
                    v.y = (gc+1<N)? B[(size_t)(k0+r)*ldb+gc+1] : 0.f;
                    v.z = (gc+2<N)? B[(size_t)(k0+r)*ldb+gc+2] : 0.f;
                    v.w = (gc+3<N)? B[(size_t)(k0+r)*ldb+gc+3] : 0.f;
                }
                Bs[r][c4+0]=v.x; Bs[r][c4+1]=v.y; Bs[r][c4+2]=v.z; Bs[r][c4+3]=v.w;
            }
        } else {
#pragma unroll
            for (int i = 0; i < 2; i++) {
                float4 v = make_float4(0.f,0.f,0.f,0.f);
                if (nval) v = *(const float4*)(B + (size_t)(bn+nrow)*ldb + k0 + j0 + i*4);
                Bs[j0+i*4+0][nrow]=v.x; Bs[j0+i*4+1][nrow]=v.y;
                Bs[j0+i*4+2][nrow]=v.z; Bs[j0+i*4+3][nrow]=v.w;
            }
        }
        __syncthreads();
#pragma unroll
        for (int kk = 0; kk < 16; kk++) {
            float a[8], b[8];
            *(float4*)(a)   = *(const float4*)&As[kk][ty*8];
            *(float4*)(a+4) = *(const float4*)&As[kk][ty*8+4];
            *(float4*)(b)   = *(const float4*)&Bs[kk][tx*8];
            *(float4*)(b+4) = *(const float4*)&Bs[kk][tx*8+4];
#pragma unroll
            for (int i=0;i<8;i++)
#pragma unroll
                for (int j=0;j<8;j++)
                    acc[i][j] = fmaf(a[i], b[j], acc[i][j]);
        }
        __syncthreads();
    }

    float* Co = C + (SPLIT ? (size_t)blockIdx.z * M * ldc : (size_t)0);
#pragma unroll
    for (int i=0;i<8;i++) {
        int r = bm + ty*8 + i;
        if (r >= M) continue;
#pragma unroll
        for (int j=0;j<8;j++) {
            int c = bn + tx*8 + j;
            if (c >= N) continue;
            float v = acc[i][j];
            if (!SPLIT) {
                v = v * scale + (bias ? bias[c] : 0.f);
                if (TANH) v = tanhf(v);
            }
            Co[(size_t)r*ldc + c] = v;
        }
    }
}

// ---------------- split-K reduces (fixed order = deterministic) ----------------
__global__ void reduce_bias_k(const float* __restrict__ P, const float* __restrict__ bias,
                              float* __restrict__ out, int total, int ld, int nsplit)
{
    int idx = blockIdx.x*blockDim.x + threadIdx.x;
    if (idx >= total) return;
    float s = 0.f;
    for (int z = 0; z < nsplit; z++) s += P[(size_t)z*total + idx];
    out[idx] = s + bias[idx % ld];
}

__global__ void reduce_scale_k(const float* __restrict__ P, const float* __restrict__ rsA,
                               const float* __restrict__ rsB, float* __restrict__ out,
                               int nsplit, float scale)
{
    int idx = blockIdx.x*blockDim.x + threadIdx.x;     // over 512*512
    float s = 0.f;
    for (int z = 0; z < nsplit; z++) s += P[(size_t)z*B_*B_ + idx];
    out[idx] = s * rsA[idx >> 9] * rsB[idx & 511] * scale;
}

// ---------------- reciprocal row norms ----------------
__global__ void norms_kernel(const float* __restrict__ LR, const float* __restrict__ rdesc,
                             const float* __restrict__ D, float* __restrict__ norms)
{
    int b = blockIdx.x, which = blockIdx.y, tid = threadIdx.x;
    const float* x; int len;
    if      (which == 0) { x = LR    + (size_t)b*NP_ + NL_;   len = DS_;  }
    else if (which == 1) { x = rdesc + (size_t)b*DS_;         len = DS_;  }
    else if (which == 2) { x = D     + (size_t)b*4*H_;        len = 2*H_; }
    else                 { x = D     + (size_t)b*4*H_ + 2*H_; len = 2*H_; }
    float s = 0.f;
    for (int i = tid; i < len; i += 256) { float v = x[i]; s += v*v; }
    __shared__ float red[256];
    red[tid] = s; __syncthreads();
    for (int st = 128; st > 0; st >>= 1) {
        if (tid < st) red[tid] += red[tid + st];
        __syncthreads();
    }
    if (tid == 0) norms[which*B_ + b] = 1.f / fmaxf(sqrtf(red[0]), EPS_);
}

// ---------------- CE on logits (cols 0..39 of LR) ----------------
__global__ void ce_kernel(const float* __restrict__ LR, const int* __restrict__ lab,
                          float* __restrict__ ce)
{
    int b = blockIdx.x * blockDim.x + threadIdx.x;
    if (b >= B_) return;
    const float* row = LR + (size_t)b * NP_;
    float mx = -INFINITY;
    for (int j = 0; j < NL_; j++) mx = fmaxf(mx, row[j]);
    float s = 0.f;
    for (int j = 0; j < NL_; j++) s += expf(row[j] - mx);
    ce[b] = mx + logf(s) - row[lab[b]];
}

// ---------------- margin on C ----------------
__global__ void margin_kernel(const float* __restrict__ Cm, const int* __restrict__ lab,
                              float* __restrict__ mout)
{
    int b = blockIdx.x, tid = threadIdx.x;
    int lb = lab[b];
    const float* row = Cm + (size_t)b * B_;
    float mx = -INFINITY;
    for (int j = tid; j < B_; j += 256)
        if (lab[j] != lb) mx = fmaxf(mx, row[j]);
    __shared__ float red[256];
    red[tid] = mx; __syncthreads();
    for (int st = 128; st > 0; st >>= 1) {
        if (tid < st) red[tid] = fmaxf(red[tid], red[tid + st]);
        __syncthreads();
    }
    if (tid == 0) {
        float neg = fmaxf(red[0], 0.f);
        mout[b] = fmaxf(neg - row[b] + GAMMA_, 0.f) * (1.0f - ALPHA_);
    }
}

// ---------------- CE on cos_sim, diag labels ----------------
__global__ void cl_kernel(const float* __restrict__ cosm, float* __restrict__ cl)
{
    int b = blockIdx.x, tid = threadIdx.x;
    const float* row = cosm + (size_t)b * B_;
    float mx = -INFINITY;
    for (int j = tid; j < B_; j += 256) mx = fmaxf(mx, row[j]);
    __shared__ float red[256];
    red[tid] = mx; __syncthreads();
    for (int st = 128; st > 0; st >>= 1) {
        if (tid < st) red[tid] = fmaxf(red[tid], red[tid + st]);
        __syncthreads();
    }
    float m = red[0]; __syncthreads();
    float s = 0.f;
    for (int j = tid; j < B_; j += 256) s += expf(row[j] - m);
    red[tid] = s; __syncthreads();
    for (int st = 128; st > 0; st >>= 1) {
        if (tid < st) red[tid] += red[tid + st];
        __syncthreads();
    }
    if (tid == 0) cl[b] = m + logf(red[0]) - row[b];
}

// ---------------- final combine ----------------
__global__ void final_kernel(const float* __restrict__ ce, const float* __restrict__ m,
                             const float* __restrict__ cl, float* __restrict__ out)
{
    int tid = threadIdx.x;
    float v = ce[tid] * (1.0f / B_) + m[tid] + (ALPHA_ / B_) * cl[tid];
    __shared__ float red[512];
    red[tid] = v; __syncthreads();
    for (int st = 256; st > 0; st >>= 1) {
        if (tid < st) red[tid] += red[tid + st];
        __syncthreads();
    }
    if (tid == 0) out[0] = red[0];
}

// ---------------- host launcher ----------------
extern "C" void kernel_launch(void* const* d_in, const int* in_sizes, int n_in,
                              void* d_out, int out_size)
{
    const float* bert    = (const float*)d_in[0];
    const float* rdesc   = (const float*)d_in[1];
    const float* dense_w = (const float*)d_in[2];
    const float* dense_b = (const float*)d_in[3];
    const float* cls_w   = (const float*)d_in[4];
    const float* cls_b   = (const float*)d_in[5];
    const float* fc_w    = (const float*)d_in[6];
    const float* fc_b    = (const float*)d_in[7];
    const int*   eidx    = (const int*)d_in[8];
    const int*   lab     = (const int*)d_in[9];
    float* out = (float*)d_out;

    float *RH,*TOKS,*W,*biasP,*P1,*LR,*D,*P2,*P3,*Cm,*cosm,*norms,*ce,*mm,*cl;
    cudaGetSymbolAddress((void**)&RH,    g_RH);
    cudaGetSymbolAddress((void**)&TOKS,  g_TOKS);
    cudaGetSymbolAddress((void**)&W,     g_W);
    cudaGetSymbolAddress((void**)&biasP, g_biasP);
    cudaGetSymbolAddress((void**)&P1,    g_P1);
    cudaGetSymbolAddress((void**)&LR,    g_LR);
    cudaGetSymbolAddress((void**)&D,     g_D);
    cudaGetSymbolAddress((void**)&P2,    g_P2);
    cudaGetSymbolAddress((void**)&P3,    g_P3);
    cudaGetSymbolAddress((void**)&Cm,    g_C);
    cudaGetSymbolAddress((void**)&cosm,  g_cos);
    cudaGetSymbolAddress((void**)&norms, g_norms);
    cudaGetSymbolAddress((void**)&ce,    g_ce);
    cudaGetSymbolAddress((void**)&mm,    g_m);
    cudaGetSymbolAddress((void**)&cl,    g_cl);

    // prep
    gather_kernel<<<B_, 192>>>(bert, eidx, RH, TOKS);
    pack_kernel<<<952, 256>>>(cls_w, fc_w, cls_b, fc_b, W, biasP);

    // dense: tanh(TOKS @ dense_w + b) -> D   [2048,768,768]
    gemm_k<false,true,false><<<dim3(12,16,1), 128>>>(TOKS, dense_w, dense_b, D,
        4*B_, H_, H_, H_, H_, H_, H_, 1.f);

    // packed: RH @ W -> P1 (split-K 6)   [512,424,2304]
    gemm_k<false,false,true><<<dim3(7,4,6), 128>>>(RH, W, nullptr, P1,
        B_, NP_, H3_, H3_, NP_, NP_, 384, 1.f);
    reduce_bias_k<<<(B_*NP_+255)/256, 256>>>(P1, biasP, LR, B_*NP_, NP_, 6);

    // reciprocal norms (rel rows, rdesc rows, z1, z2)
    norms_kernel<<<dim3(B_,4,1), 256>>>(LR, rdesc, D, norms);

    // C = rel @ rdesc^T (split-K 2)   [512,512,384]
    gemm_k<true,false,true><<<dim3(8,4,2), 128>>>(LR + NL_, rdesc, nullptr, P2,
        B_, B_, DS_, NP_, DS_, B_, 192, 1.f);
    reduce_scale_k<<<(B_*B_)/256, 256>>>(P2, norms + 0*B_, norms + 1*B_, Cm, 2, 1.f);

    // cos = z1 @ z2^T (split-K 4)   [512,512,1536]
    gemm_k<true,false,true><<<dim3(8,4,4), 128>>>(D, D + 2*H_, nullptr, P3,
        B_, B_, 2*H_, 4*H_, 4*H_, B_, 384, 1.f);
    reduce_scale_k<<<(B_*B_)/256, 256>>>(P3, norms + 2*B_, norms + 3*B_, cosm, 4, TEMP_INV_);

    // losses
    ce_kernel<<<2, 256>>>(LR, lab, ce);
    margin_kernel<<<B_, 256>>>(Cm, lab, mm);
    cl_kernel<<<B_, 256>>>(cosm, cl);
    final_kernel<<<1, 512>>>(ce, mm, cl, out);
}

// round 4
// speedup vs baseline: 2.6698x; 1.5552x over previous
#include <cuda_runtime.h>
#include <math.h>

#define B_    512
#define S_    128
#define H_    768
#define DS_   384
#define NL_   40
#define H3_   2304
#define NP_   424          // packed N = 40 + 384
#define TEMP_INV_ 20.0f
#define ALPHA_    0.15f
#define GAMMA_    7.5f
#define EPS_      1e-8f

// ---------------- scratch ----------------
__device__ float g_RH[B_ * H3_];          // tanh(concat) 512x2304
__device__ float g_TOKS[B_ * 4 * H_];     // 2048x768
__device__ float g_W[H3_ * NP_];          // packed [2304,424]
__device__ float g_biasP[NP_];
__device__ float g_Pd[2 * B_ * 4 * H_];   // dense split-K partials
__device__ float g_P1[9 * B_ * NP_];      // packed gemm partials
__device__ float g_LR[B_ * NP_];          // logits(0..39) | rel(40..423)
__device__ float g_D[B_ * 4 * H_];        // tanh(toks@dense_w+b) 2048x768
__device__ float g_P2[6 * B_ * B_];       // C partials
__device__ float g_P3[8 * B_ * B_];       // cos partials
__device__ float g_C[B_ * B_];
__device__ float g_cos[B_ * B_];
__device__ float g_norms[4 * B_];         // recip norms: rel, rdesc, z1, z2
__device__ float g_ce[B_];
__device__ float g_m[B_];
__device__ float g_cl[B_];

// ---------------- gather + tanh (float4) ----------------
__global__ void gather_kernel(const float* __restrict__ bert,
                              const int* __restrict__ eidx,
                              float* __restrict__ RH,
                              float* __restrict__ TOKS)
{
    int b = blockIdx.x, t = threadIdx.x;        // t in 0..191
    const float* base0 = bert + (size_t)b * 2 * S_ * H_;
    const float* base1 = base0 + S_ * H_;
    int i0 = eidx[b*4+0], i1 = eidx[b*4+1], i2 = eidx[b*4+2], i3 = eidx[b*4+3];
    float4 c  = ((const float4*)base0)[t];
    float4 hh = ((const float4*)(base0 + (size_t)i0*H_))[t];
    float4 tl = ((const float4*)(base0 + (size_t)i1*H_))[t];
    float4 a2 = ((const float4*)(base1 + (size_t)i2*H_))[t];
    float4 b2 = ((const float4*)(base1 + (size_t)i3*H_))[t];
    float4* rh = (float4*)(RH + (size_t)b*H3_);
    float4* tk = (float4*)(TOKS + (size_t)b*4*H_);
    rh[t]     = make_float4(tanhf(c.x),tanhf(c.y),tanhf(c.z),tanhf(c.w));
    rh[192+t] = make_float4(tanhf(hh.x),tanhf(hh.y),tanhf(hh.z),tanhf(hh.w));
    rh[384+t] = make_float4(tanhf(tl.x),tanhf(tl.y),tanhf(tl.z),tanhf(tl.w));
    tk[t] = hh; tk[192+t] = tl; tk[384+t] = a2; tk[576+t] = b2;
}

// ---------------- pack weights ----------------
__global__ void pack_kernel(const float* __restrict__ cls_w, const float* __restrict__ fc_w,
                            const float* __restrict__ cls_b, const float* __restrict__ fc_b,
                            float* __restrict__ W, float* __restrict__ biasP)
{
    int idx = blockIdx.x*blockDim.x + threadIdx.x;
    const int total = H3_ * NP_;
    for (int i = idx; i < total; i += gridDim.x*blockDim.x) {
        int k = i / NP_, c = i % NP_;
        W[i] = (c < NL_) ? cls_w[(size_t)k*NL_ + c] : fc_w[(size_t)k*DS_ + (c-NL_)];
    }
    if (idx < NP_) biasP[idx] = (idx < NL_) ? cls_b[idx] : fc_b[idx-NL_];
}

// ============ 128x128 tile GEMM, 256 thr, 8x8/thread, reg-prefetch pipeline ============
// Partial C[z] = A[M,K-chunk] @ B ; M must be a multiple of 128; K chunk multiple of 16.
// NT=false: B is [K,N] row-major ; NT=true: B is [N,K] row-major (B transposed)
template<bool NT>
__global__ __launch_bounds__(256, 2)
void gemm_t(const float* __restrict__ A, const float* __restrict__ B,
            float* __restrict__ C,
            int M, int N, int K, int lda, int ldb, int ldc, int kChunk)
{
    __shared__ float As[16][132];
    __shared__ float Bs[16][132];
    const int tid = threadIdx.x;
    const int bm = blockIdx.y * 128, bn = blockIdx.x * 128;
    const int tx = tid & 15, ty = tid >> 4;

    const int kBeg = blockIdx.z * kChunk;
    const int kEnd = min(K, kBeg + kChunk);

    // A load mapping: row = tid>>1 (0..127), k-off = (tid&1)*8
    const int arow = tid >> 1;
    const int ak   = (tid & 1) * 8;
    const float* Ap = A + (size_t)(bm + arow) * lda + ak;

    // B mapping
    const int b_nn_r = tid >> 4;            // 0..15 (k row)
    const int b_nn_c = (tid & 15) * 8;      // 0..120 (n col)
    const int gc     = bn + b_nn_c;
    const float* Bp_nn = B + (size_t)b_nn_r * ldb + gc;
    const float* Bp_nt = B + (size_t)(bn + arow) * ldb + ak;

    float4 pa0, pa1, pb0, pb1;

    // prologue: prefetch first k-tile
    {
        const float* a = Ap + kBeg;
        pa0 = *(const float4*)(a);
        pa1 = *(const float4*)(a + 4);
        if (!NT) {
            const float* bq = Bp_nn + (size_t)kBeg * ldb;
            if (gc + 7 < N) { pb0 = *(const float4*)bq; pb1 = *(const float4*)(bq + 4); }
            else {
                float t[8];
                #pragma unroll
                for (int u = 0; u < 8; u++) t[u] = (gc + u < N) ? bq[u] : 0.f;
                pb0 = make_float4(t[0],t[1],t[2],t[3]);
                pb1 = make_float4(t[4],t[5],t[6],t[7]);
            }
        } else {
            const float* bq = Bp_nt + kBeg;
            pb0 = *(const float4*)bq; pb1 = *(const float4*)(bq + 4);
        }
    }

    float acc[8][8];
#pragma unroll
    for (int i=0;i<8;i++)
#pragma unroll
        for (int j=0;j<8;j++) acc[i][j]=0.f;

    for (int k0 = kBeg; k0 < kEnd; k0 += 16) {
        // commit prefetched tile to smem
        As[ak+0][arow]=pa0.x; As[ak+1][arow]=pa0.y; As[ak+2][arow]=pa0.z; As[ak+3][arow]=pa0.w;
        As[ak+4][arow]=pa1.x; As[ak+5][arow]=pa1.y; As[ak+6][arow]=pa1.z; As[ak+7][arow]=pa1.w;
        if (!NT) {
            Bs[b_nn_r][b_nn_c+0]=pb0.x; Bs[b_nn_r][b_nn_c+1]=pb0.y;
            Bs[b_nn_r][b_nn_c+2]=pb0.z; Bs[b_nn_r][b_nn_c+3]=pb0.w;
            Bs[b_nn_r][b_nn_c+4]=pb1.x; Bs[b_nn_r][b_nn_c+5]=pb1.y;
            Bs[b_nn_r][b_nn_c+6]=pb1.z; Bs[b_nn_r][b_nn_c+7]=pb1.w;
        } else {
            Bs[ak+0][arow]=pb0.x; Bs[ak+1][arow]=pb0.y; Bs[ak+2][arow]=pb0.z; Bs[ak+3][arow]=pb0.w;
            Bs[ak+4][arow]=pb1.x; Bs[ak+5][arow]=pb1.y; Bs[ak+6][arow]=pb1.z; Bs[ak+7][arow]=pb1.w;
        }
        __syncthreads();

        // prefetch next k-tile while computing this one
        int kn = k0 + 16;
        if (kn < kEnd) {
            const float* a = Ap + kn;
            pa0 = *(const float4*)(a);
            pa1 = *(const float4*)(a + 4);
            if (!NT) {
                const float* bq = Bp_nn + (size_t)kn * ldb;
                if (gc + 7 < N) { pb0 = *(const float4*)bq; pb1 = *(const float4*)(bq + 4); }
                else {
                    float t[8];
                    #pragma unroll
                    for (int u = 0; u < 8; u++) t[u] = (gc + u < N) ? bq[u] : 0.f;
                    pb0 = make_float4(t[0],t[1],t[2],t[3]);
                    pb1 = make_float4(t[4],t[5],t[6],t[7]);
                }
            } else {
                const float* bq = Bp_nt + kn;
                pb0 = *(const float4*)bq; pb1 = *(const float4*)(bq + 4);
            }
        }

#pragma unroll
        for (int kk = 0; kk < 16; kk++) {
            float a[8], b[8];
            *(float4*)(a)   = *(const float4*)&As[kk][ty*8];
            *(float4*)(a+4) = *(const float4*)&As[kk][ty*8+4];
            *(float4*)(b)   = *(const float4*)&Bs[kk][tx*8];
            *(float4*)(b+4) = *(const float4*)&Bs[kk][tx*8+4];
#pragma unroll
            for (int i=0;i<8;i++)
#pragma unroll
                for (int j=0;j<8;j++)
                    acc[i][j] = fmaf(a[i], b[j], acc[i][j]);
        }
        __syncthreads();
    }

    float* Co = C + (size_t)blockIdx.z * M * ldc;
#pragma unroll
    for (int i=0;i<8;i++) {
        int r = bm + ty*8 + i;
#pragma unroll
        for (int j=0;j<8;j+=4) {
            int c = bn + tx*8 + j;
            if (c + 3 < N) {
                *(float4*)(Co + (size_t)r*ldc + c) =
                    make_float4(acc[i][j],acc[i][j+1],acc[i][j+2],acc[i][j+3]);
            } else {
                #pragma unroll
                for (int u = 0; u < 4; u++)
                    if (c + u < N) Co[(size_t)r*ldc + c + u] = acc[i][j+u];
            }
        }
    }
}

// ---------------- split-K reduce: out = [tanh](sum_z P + bias) ----------------
template<bool TANH>
__global__ void reduce_bias_k(const float* __restrict__ P, const float* __restrict__ bias,
                              float* __restrict__ out, int total, int ld, int nsplit)
{
    int idx = blockIdx.x*blockDim.x + threadIdx.x;
    if (idx >= total) return;
    float s = bias[idx % ld];
    for (int z = 0; z < nsplit; z++) s += P[(size_t)z*total + idx];
    out[idx] = TANH ? tanhf(s) : s;
}

// ---------------- split-K reduce with norm scaling ----------------
__global__ void reduce_scale_k(const float* __restrict__ P, const float* __restrict__ rsA,
                               const float* __restrict__ rsB, float* __restrict__ out,
                               int nsplit, float scale)
{
    int idx = blockIdx.x*blockDim.x + threadIdx.x;     // over 512*512
    float s = 0.f;
    for (int z = 0; z < nsplit; z++) s += P[(size_t)z*B_*B_ + idx];
    out[idx] = s * rsA[idx >> 9] * rsB[idx & 511] * scale;
}

// ---------------- reciprocal row norms ----------------
__global__ void norms_kernel(const float* __restrict__ LR, const float* __restrict__ rdesc,
                             const float* __restrict__ D, float* __restrict__ norms)
{
    int b = blockIdx.x, which = blockIdx.y, tid = threadIdx.x;
    const float* x; int len;
    if      (which == 0) { x = LR    + (size_t)b*NP_ + NL_;   len = DS_;  }
    else if (which == 1) { x = rdesc + (size_t)b*DS_;         len = DS_;  }
    else if (which == 2) { x = D     + (size_t)b*4*H_;        len = 2*H_; }
    else                 { x = D     + (size_t)b*4*H_ + 2*H_; len = 2*H_; }
    float s = 0.f;
    for (int i = tid; i < len; i += 256) { float v = x[i]; s += v*v; }
    __shared__ float red[256];
    red[tid] = s; __syncthreads();
    for (int st = 128; st > 0; st >>= 1) {
        if (tid < st) red[tid] += red[tid + st];
        __syncthreads();
    }
    if (tid == 0) norms[which*B_ + b] = 1.f / fmaxf(sqrtf(red[0]), EPS_);
}

// ---------------- CE on logits (cols 0..39 of LR) ----------------
__global__ void ce_kernel(const float* __restrict__ LR, const int* __restrict__ lab,
                          float* __restrict__ ce)
{
    int b = blockIdx.x * blockDim.x + threadIdx.x;
    if (b >= B_) return;
    const float* row = LR + (size_t)b * NP_;
    float mx = -INFINITY;
    for (int j = 0; j < NL_; j++) mx = fmaxf(mx, row[j]);
    float s = 0.f;
    for (int j = 0; j < NL_; j++) s += expf(row[j] - mx);
    ce[b] = mx + logf(s) - row[lab[b]];
}

// ---------------- margin on C ----------------
__global__ void margin_kernel(const float* __restrict__ Cm, const int* __restrict__ lab,
                              float* __restrict__ mout)
{
    int b = blockIdx.x, tid = threadIdx.x;
    int lb = lab[b];
    const float* row = Cm + (size_t)b * B_;
    float mx = -INFINITY;
    for (int j = tid; j < B_; j += 256)
        if (lab[j] != lb) mx = fmaxf(mx, row[j]);
    __shared__ float red[256];
    red[tid] = mx; __syncthreads();
    for (int st = 128; st > 0; st >>= 1) {
        if (tid < st) red[tid] = fmaxf(red[tid], red[tid + st]);
        __syncthreads();
    }
    if (tid == 0) {
        float neg = fmaxf(red[0], 0.f);
        mout[b] = fmaxf(neg - row[b] + GAMMA_, 0.f) * (1.0f - ALPHA_);
    }
}

// ---------------- CE on cos_sim, diag labels ----------------
__global__ void cl_kernel(const float* __restrict__ cosm, float* __restrict__ cl)
{
    int b = blockIdx.x, tid = threadIdx.x;
    const float* row = cosm + (size_t)b * B_;
    float mx = -INFINITY;
    for (int j = tid; j < B_; j += 256) mx = fmaxf(mx, row[j]);
    __shared__ float red[256];
    red[tid] = mx; __syncthreads();
    for (int st = 128; st > 0; st >>= 1) {
        if (tid < st) red[tid] = fmaxf(red[tid], red[tid + st]);
        __syncthreads();
    }
    float m = red[0]; __syncthreads();
    float s = 0.f;
    for (int j = tid; j < B_; j += 256) s += expf(row[j] - m);
    red[tid] = s; __syncthreads();
    for (int st = 128; st > 0; st >>= 1) {
        if (tid < st) red[tid] += red[tid + st];
        __syncthreads();
    }
    if (tid == 0) cl[b] = m + logf(red[0]) - row[b];
}

// ---------------- final combine ----------------
__global__ void final_kernel(const float* __restrict__ ce, const float* __restrict__ m,
                             const float* __restrict__ cl, float* __restrict__ out)
{
    int tid = threadIdx.x;
    float v = ce[tid] * (1.0f / B_) + m[tid] + (ALPHA_ / B_) * cl[tid];
    __shared__ float red[512];
    red[tid] = v; __syncthreads();
    for (int st = 256; st > 0; st >>= 1) {
        if (tid < st) red[tid] += red[tid + st];
        __syncthreads();
    }
    if (tid == 0) out[0] = red[0];
}

// ---------------- host launcher ----------------
extern "C" void kernel_launch(void* const* d_in, const int* in_sizes, int n_in,
                              void* d_out, int out_size)
{
    const float* bert    = (const float*)d_in[0];
    const float* rdesc   = (const float*)d_in[1];
    const float* dense_w = (const float*)d_in[2];
    const float* dense_b = (const float*)d_in[3];
    const float* cls_w   = (const float*)d_in[4];
    const float* cls_b   = (const float*)d_in[5];
    const float* fc_w    = (const float*)d_in[6];
    const float* fc_b    = (const float*)d_in[7];
    const int*   eidx    = (const int*)d_in[8];
    const int*   lab     = (const int*)d_in[9];
    float* out = (float*)d_out;

    float *RH,*TOKS,*W,*biasP,*Pd,*P1,*LR,*D,*P2,*P3,*Cm,*cosm,*norms,*ce,*mm,*cl;
    cudaGetSymbolAddress((void**)&RH,    g_RH);
    cudaGetSymbolAddress((void**)&TOKS,  g_TOKS);
    cudaGetSymbolAddress((void**)&W,     g_W);
    cudaGetSymbolAddress((void**)&biasP, g_biasP);
    cudaGetSymbolAddress((void**)&Pd,    g_Pd);
    cudaGetSymbolAddress((void**)&P1,    g_P1);
    cudaGetSymbolAddress((void**)&LR,    g_LR);
    cudaGetSymbolAddress((void**)&D,     g_D);
    cudaGetSymbolAddress((void**)&P2,    g_P2);
    cudaGetSymbolAddress((void**)&P3,    g_P3);
    cudaGetSymbolAddress((void**)&Cm,    g_C);
    cudaGetSymbolAddress((void**)&cosm,  g_cos);
    cudaGetSymbolAddress((void**)&norms, g_norms);
    cudaGetSymbolAddress((void**)&ce,    g_ce);
    cudaGetSymbolAddress((void**)&mm,    g_m);
    cudaGetSymbolAddress((void**)&cl,    g_cl);

    // prep
    gather_kernel<<<B_, 192>>>(bert, eidx, RH, TOKS);
    pack_kernel<<<952, 256>>>(cls_w, fc_w, cls_b, fc_b, W, biasP);

    // dense: TOKS @ dense_w  [2048,768,768]  split-K 2 -> Pd, then tanh(+bias) reduce -> D
    gemm_t<false><<<dim3(6,16,2), 256>>>(TOKS, dense_w, Pd,
        4*B_, H_, H_, H_, H_, H_, 384);
    reduce_bias_k<true><<<(4*B_*H_+255)/256, 256>>>(Pd, dense_b, D, 4*B_*H_, H_, 2);

    // packed: RH @ W  [512,424,2304]  split-K 9 -> P1, then +bias reduce -> LR
    gemm_t<false><<<dim3(4,4,9), 256>>>(RH, W, P1,
        B_, NP_, H3_, H3_, NP_, NP_, 256);
    reduce_bias_k<false><<<(B_*NP_+255)/256, 256>>>(P1, biasP, LR, B_*NP_, NP_, 9);

    // reciprocal norms (rel rows, rdesc rows, z1, z2)
    norms_kernel<<<dim3(B_,4,1), 256>>>(LR, rdesc, D, norms);

    // C = rel @ rdesc^T  [512,512,384]  split-K 6
    gemm_t<true><<<dim3(4,4,6), 256>>>(LR + NL_, rdesc, P2,
        B_, B_, DS_, NP_, DS_, B_, 64);
    reduce_scale_k<<<(B_*B_)/256, 256>>>(P2, norms + 0*B_, norms + 1*B_, Cm, 6, 1.f);

    // cos = z1 @ z2^T  [512,512,1536]  split-K 8
    gemm_t<true><<<dim3(4,4,8), 256>>>(D, D + 2*H_, P3,
        B_, B_, 2*H_, 4*H_, 4*H_, B_, 192);
    reduce_scale_k<<<(B_*B_)/256, 256>>>(P3, norms + 2*B_, norms + 3*B_, cosm, 8, TEMP_INV_);

    // losses
    ce_kernel<<<2, 256>>>(LR, lab, ce);
    margin_kernel<<<B_, 256>>>(Cm, lab, mm);
    cl_kernel<<<B_, 256>>>(cosm, cl);
    final_kernel<<<1, 512>>>(ce, mm, cl, out);
}

// round 6
// speedup vs baseline: 5.1201x; 1.9178x over previous
#include <cuda_runtime.h>
#include <cuda_bf16.h>
#include <math.h>
#include <stdint.h>

#define B_    512
#define S_    128
#define H_    768
#define DS_   384
#define NL_   40
#define H3_   2304
#define NP2_  448          // packed N padded to 7*64
#define TEMP_INV_ 20.0f
#define ALPHA_    0.15f
#define GAMMA_    7.5f
#define EPS_      1e-8f

// ---------------- scratch ----------------
__device__ __nv_bfloat16 g_RHb[B_ * H3_];        // tanh(concat) bf16  512x2304
__device__ __nv_bfloat16 g_TOKSb[B_ * 4 * H_];   // bf16 2048x768
__device__ __nv_bfloat16 g_Wd[H_ * H_];          // dense_w^T bf16 [768,768] (N,K)
__device__ __nv_bfloat16 g_Wp[NP2_ * H3_];       // packed W^T bf16 [448,2304]
__device__ __nv_bfloat16 g_rdescb[B_ * DS_];     // rdesc bf16
__device__ __nv_bfloat16 g_relb[B_ * DS_];       // rel bf16
__device__ __nv_bfloat16 g_Db[B_ * 4 * H_];      // tanh dense out bf16 2048x768
__device__ float g_biasP[NP2_];
__device__ float g_P1[6 * B_ * NP2_];            // packed partials
__device__ float g_LR[B_ * NP2_];                // logits(0..39) | rel(40..423)
__device__ float g_D[B_ * 4 * H_];               // tanh dense out fp32
__device__ float g_P2[3 * B_ * B_];              // C partials
__device__ float g_P3[4 * B_ * B_];              // cos partials
__device__ float g_C[B_ * B_];
__device__ float g_cos[B_ * B_];
__device__ float g_norms[4 * B_];                // recip norms: rel, rdesc, z1, z2
__device__ float g_ce[B_];
__device__ float g_m[B_];
__device__ float g_cl[B_];

__device__ __forceinline__ uint32_t smem_u32(const void* p) {
    uint32_t a;
    asm("{ .reg .u64 t; cvta.to.shared.u64 t, %1; cvt.u32.u64 %0, t; }" : "=r"(a) : "l"(p));
    return a;
}

// ================= mma.sync bf16 NT GEMM =================
// D[128x64 tile] = A[M,K](bf16 rm, lda) @ B[N,K]^T (bf16 rm, ldb)
// K from kBeg=z*kChunk, kChunk % 64 == 0. 8 warps: 4(M) x 2(N); warp tile 32x32.
// MODE 0: raw fp32 -> C + z*M*ldc
// MODE 1: tanh(acc + bias) -> C fp32 and Obf bf16 (both ldc)
#define KT_ 64
#define SPAD_ 72
template<int MODE>
__global__ __launch_bounds__(256, 2)
void mma_nt(const __nv_bfloat16* __restrict__ A, const __nv_bfloat16* __restrict__ B,
            float* __restrict__ C, const float* __restrict__ bias,
            __nv_bfloat16* __restrict__ Obf,
            int M, int N, int K, int lda, int ldb, int ldc, int kChunk)
{
    __shared__ __nv_bfloat16 sA[128][SPAD_];
    __shared__ __nv_bfloat16 sB[64][SPAD_];

    const int tid  = threadIdx.x;
    const int warp = tid >> 5, lane = tid & 31;
    const int wm = warp >> 1, wn = warp & 1;           // 4 x 2 warps
    const int bm = blockIdx.y * 128, bn = blockIdx.x * 64;
    const int kBeg = blockIdx.z * kChunk;
    const int kEnd = kBeg + kChunk;

    // global load mapping
    const int arow = tid >> 1, ac0 = (tid & 1) * 32;   // A: 4 x uint4 per thread
    const int brow = tid >> 2, bc0 = (tid & 3) * 16;   // B: 2 x uint4 per thread

    // ldmatrix source addresses (constant across k-tiles except column)
    const int alr = lane & 15, alc = (lane >> 4) << 3;
    const int blr = lane & 7,  blc = ((lane >> 3) & 1) << 3;

    float acc[2][4][4];
#pragma unroll
    for (int mi = 0; mi < 2; mi++)
#pragma unroll
        for (int ni = 0; ni < 4; ni++)
#pragma unroll
            for (int r = 0; r < 4; r++) acc[mi][ni][r] = 0.f;

    for (int k0 = kBeg; k0 < kEnd; k0 += KT_) {
        // stage A tile (128 x 64)
        const __nv_bfloat16* ag = A + (size_t)(bm + arow) * lda + k0 + ac0;
#pragma unroll
        for (int j = 0; j < 4; j++)
            *(uint4*)&sA[arow][ac0 + j * 8] = *(const uint4*)(ag + j * 8);
        // stage B tile (64 x 64)
        const __nv_bfloat16* bg = B + (size_t)(bn + brow) * ldb + k0 + bc0;
#pragma unroll
        for (int j = 0; j < 2; j++)
            *(uint4*)&sB[brow][bc0 + j * 8] = *(const uint4*)(bg + j * 8);
        __syncthreads();

#pragma unroll
        for (int ks = 0; ks < KT_ / 16; ks++) {
            const int kk = ks * 16;
            uint32_t a[2][4], b[4][2];
#pragma unroll
            for (int mi = 0; mi < 2; mi++) {
                uint32_t addr = smem_u32(&sA[wm * 32 + mi * 16 + alr][kk + alc]);
                asm volatile("ldmatrix.sync.aligned.m8n8.x4.shared.b16 {%0,%1,%2,%3}, [%4];"
                             : "=r"(a[mi][0]), "=r"(a[mi][1]), "=r"(a[mi][2]), "=r"(a[mi][3])
                             : "r"(addr));
            }
#pragma unroll
            for (int ni = 0; ni < 4; ni++) {
                uint32_t addr = smem_u32(&sB[wn * 32 + ni * 8 + blr][kk + blc]);
                asm volatile("ldmatrix.sync.aligned.m8n8.x2.shared.b16 {%0,%1}, [%2];"
                             : "=r"(b[ni][0]), "=r"(b[ni][1]) : "r"(addr));
            }
#pragma unroll
            for (int mi = 0; mi < 2; mi++)
#pragma unroll
                for (int ni = 0; ni < 4; ni++) {
                    asm volatile(
                        "mma.sync.aligned.m16n8k16.row.col.f32.bf16.bf16.f32 "
                        "{%0,%1,%2,%3}, {%4,%5,%6,%7}, {%8,%9}, {%0,%1,%2,%3};"
                        : "+f"(acc[mi][ni][0]), "+f"(acc[mi][ni][1]),
                          "+f"(acc[mi][ni][2]), "+f"(acc[mi][ni][3])
                        : "r"(a[mi][0]), "r"(a[mi][1]), "r"(a[mi][2]), "r"(a[mi][3]),
                          "r"(b[ni][0]), "r"(b[ni][1]));
                }
        }
        __syncthreads();
    }

    // epilogue: lane layout of m16n8 acc: rows g=lane>>2 (+8), cols (lane&3)*2 (+1)
    const int g = lane >> 2, cpair = (lane & 3) * 2;
#pragma unroll
    for (int mi = 0; mi < 2; mi++) {
#pragma unroll
        for (int half = 0; half < 2; half++) {
            const int row = bm + wm * 32 + mi * 16 + g + half * 8;
#pragma unroll
            for (int ni = 0; ni < 4; ni++) {
                const int col = bn + wn * 32 + ni * 8 + cpair;
                float v0 = acc[mi][ni][half * 2 + 0];
                float v1 = acc[mi][ni][half * 2 + 1];
                if (MODE == 0) {
                    float* Co = C + (size_t)blockIdx.z * M * ldc + (size_t)row * ldc + col;
                    Co[0] = v0; Co[1] = v1;
                } else {
                    float t0 = tanhf(v0 + bias[col]);
                    float t1 = tanhf(v1 + bias[col + 1]);
                    float* Co = C + (size_t)row * ldc + col;
                    Co[0] = t0; Co[1] = t1;
                    *(__nv_bfloat162*)(Obf + (size_t)row * ldc + col) =
                        __floats2bfloat162_rn(t0, t1);
                }
            }
        }
    }
}

// ---------------- gather + tanh -> bf16 ----------------
__global__ void gather_kernel(const float* __restrict__ bert,
                              const int* __restrict__ eidx,
                              __nv_bfloat16* __restrict__ RHb,
                              __nv_bfloat16* __restrict__ TOKSb)
{
    int b = blockIdx.x, t = threadIdx.x;  // 0..191 (float4 groups)
    const float* base0 = bert + (size_t)b * 2 * S_ * H_;
    const float* base1 = base0 + S_ * H_;
    int i0 = eidx[b*4+0], i1 = eidx[b*4+1], i2 = eidx[b*4+2], i3 = eidx[b*4+3];
    float4 c  = ((const float4*)base0)[t];
    float4 hh = ((const float4*)(base0 + (size_t)i0*H_))[t];
    float4 tl = ((const float4*)(base0 + (size_t)i1*H_))[t];
    float4 a2 = ((const float4*)(base1 + (size_t)i2*H_))[t];
    float4 b2 = ((const float4*)(base1 + (size_t)i3*H_))[t];

    __nv_bfloat162* rh = (__nv_bfloat162*)(RHb + (size_t)b * H3_);
    __nv_bfloat162* tk = (__nv_bfloat162*)(TOKSb + (size_t)b * 4 * H_);
    rh[2*t]       = __floats2bfloat162_rn(tanhf(c.x),  tanhf(c.y));
    rh[2*t+1]     = __floats2bfloat162_rn(tanhf(c.z),  tanhf(c.w));
    rh[384+2*t]   = __floats2bfloat162_rn(tanhf(hh.x), tanhf(hh.y));
    rh[384+2*t+1] = __floats2bfloat162_rn(tanhf(hh.z), tanhf(hh.w));
    rh[768+2*t]   = __floats2bfloat162_rn(tanhf(tl.x), tanhf(tl.y));
    rh[768+2*t+1] = __floats2bfloat162_rn(tanhf(tl.z), tanhf(tl.w));
    tk[2*t]        = __floats2bfloat162_rn(hh.x, hh.y);
    tk[2*t+1]      = __floats2bfloat162_rn(hh.z, hh.w);
    tk[384+2*t]    = __floats2bfloat162_rn(tl.x, tl.y);
    tk[384+2*t+1]  = __floats2bfloat162_rn(tl.z, tl.w);
    tk[768+2*t]    = __floats2bfloat162_rn(a2.x, a2.y);
    tk[768+2*t+1]  = __floats2bfloat162_rn(a2.z, a2.w);
    tk[1152+2*t]   = __floats2bfloat162_rn(b2.x, b2.y);
    tk[1152+2*t+1] = __floats2bfloat162_rn(b2.z, b2.w);
}

// ---------------- build transposed bf16 weights ----------------
__global__ void pack_kernel(const float* __restrict__ dense_w,
                            const float* __restrict__ cls_w, const float* __restrict__ fc_w,
                            const float* __restrict__ cls_b, const float* __restrict__ fc_b,
                            const float* __restrict__ rdesc,
                            __nv_bfloat16* __restrict__ Wd, __nv_bfloat16* __restrict__ Wp,
                            __nv_bfloat16* __restrict__ rdescb, float* __restrict__ biasP)
{
    int idx = blockIdx.x * blockDim.x + threadIdx.x;
    int stride = gridDim.x * blockDim.x;
    for (int i = idx; i < H_ * H_; i += stride) {
        int n = i / H_, k = i % H_;
        Wd[i] = __float2bfloat16_rn(dense_w[(size_t)k * H_ + n]);
    }
    for (int i = idx; i < NP2_ * H3_; i += stride) {
        int n = i / H3_, k = i % H3_;
        float v = 0.f;
        if (n < NL_)            v = cls_w[(size_t)k * NL_ + n];
        else if (n < NL_ + DS_) v = fc_w[(size_t)k * DS_ + (n - NL_)];
        Wp[i] = __float2bfloat16_rn(v);
    }
    for (int i = idx; i < B_ * DS_; i += stride)
        rdescb[i] = __float2bfloat16_rn(rdesc[i]);
    if (idx < NP2_)
        biasP[idx] = (idx < NL_) ? cls_b[idx] : ((idx < NL_ + DS_) ? fc_b[idx - NL_] : 0.f);
}

// ---------------- packed reduce: LR = sum P1 + bias; also emit rel bf16 ----------------
__global__ void reduce_packed_k(const float* __restrict__ P, const float* __restrict__ bias,
                                float* __restrict__ LR, __nv_bfloat16* __restrict__ relb)
{
    int idx = blockIdx.x * blockDim.x + threadIdx.x;
    const int total = B_ * NP2_;
    if (idx >= total) return;
    int c = idx % NP2_;
    float s = bias[c];
    for (int z = 0; z < 6; z++) s += P[(size_t)z * total + idx];
    LR[idx] = s;
    if (c >= NL_ && c < NL_ + DS_)
        relb[(size_t)(idx / NP2_) * DS_ + (c - NL_)] = __float2bfloat16_rn(s);
}

// ---------------- split-K reduce with norm scaling ----------------
__global__ void reduce_scale_k(const float* __restrict__ P, const float* __restrict__ rsA,
                               const float* __restrict__ rsB, float* __restrict__ out,
                               int nsplit, float scale)
{
    int idx = blockIdx.x * blockDim.x + threadIdx.x;  // over 512*512
    float s = 0.f;
    for (int z = 0; z < nsplit; z++) s += P[(size_t)z * B_ * B_ + idx];
    out[idx] = s * rsA[idx >> 9] * rsB[idx & 511] * scale;
}

// ---------------- reciprocal row norms ----------------
__global__ void norms_kernel(const float* __restrict__ LR, const float* __restrict__ rdesc,
                             const float* __restrict__ D, float* __restrict__ norms)
{
    int b = blockIdx.x, which = blockIdx.y, tid = threadIdx.x;
    const float* x; int len;
    if      (which == 0) { x = LR    + (size_t)b * NP2_ + NL_;     len = DS_;  }
    else if (which == 1) { x = rdesc + (size_t)b * DS_;            len = DS_;  }
    else if (which == 2) { x = D     + (size_t)b * 4 * H_;         len = 2*H_; }
    else                 { x = D     + (size_t)b * 4 * H_ + 2*H_;  len = 2*H_; }
    float s = 0.f;
    for (int i = tid; i < len; i += 256) { float v = x[i]; s += v * v; }
    __shared__ float red[256];
    red[tid] = s; __syncthreads();
    for (int st = 128; st > 0; st >>= 1) {
        if (tid < st) red[tid] += red[tid + st];
        __syncthreads();
    }
    if (tid == 0) norms[which * B_ + b] = 1.f / fmaxf(sqrtf(red[0]), EPS_);
}

// ---------------- CE on logits ----------------
__global__ void ce_kernel(const float* __restrict__ LR, const int* __restrict__ lab,
                          float* __restrict__ ce)
{
    int b = blockIdx.x * blockDim.x + threadIdx.x;
    if (b >= B_) return;
    const float* row = LR + (size_t)b * NP2_;
    float mx = -INFINITY;
    for (int j = 0; j < NL_; j++) mx = fmaxf(mx, row[j]);
    float s = 0.f;
    for (int j = 0; j < NL_; j++) s += expf(row[j] - mx);
    ce[b] = mx + logf(s) - row[lab[b]];
}

// ---------------- margin on C ----------------
__global__ void margin_kernel(const float* __restrict__ Cm, const int* __restrict__ lab,
                              float* __restrict__ mout)
{
    int b = blockIdx.x, tid = threadIdx.x;
    int lb = lab[b];
    const float* row = Cm + (size_t)b * B_;
    float mx = -INFINITY;
    for (int j = tid; j < B_; j += 256)
        if (lab[j] != lb) mx = fmaxf(mx, row[j]);
    __shared__ float red[256];
    red[tid] = mx; __syncthreads();
    for (int st = 128; st > 0; st >>= 1) {
        if (tid < st) red[tid] = fmaxf(red[tid], red[tid + st]);
        __syncthreads();
    }
    if (tid == 0) {
        float neg = fmaxf(red[0], 0.f);
        mout[b] = fmaxf(neg - row[b] + GAMMA_, 0.f) * (1.0f - ALPHA_);
    }
}

// ---------------- CE on cos_sim, diag labels ----------------
__global__ void cl_kernel(const float* __restrict__ cosm, float* __restrict__ cl)
{
    int b = blockIdx.x, tid = threadIdx.x;
    const float* row = cosm + (size_t)b * B_;
    float mx = -INFINITY;
    for (int j = tid; j < B_; j += 256) mx = fmaxf(mx, row[j]);
    __shared__ float red[256];
    red[tid] = mx; __syncthreads();
    for (int st = 128; st > 0; st >>= 1) {
        if (tid < st) red[tid] = fmaxf(red[tid], red[tid + st]);
        __syncthreads();
    }
    float m = red[0]; __syncthreads();
    float s = 0.f;
    for (int j = tid; j < B_; j += 256) s += expf(row[j] - m);
    red[tid] = s; __syncthreads();
    for (int st = 128; st > 0; st >>= 1) {
        if (tid < st) red[tid] += red[tid + st];
        __syncthreads();
    }
    if (tid == 0) cl[b] = m + logf(red[0]) - row[b];
}

// ---------------- final combine ----------------
__global__ void final_kernel(const float* __restrict__ ce, const float* __restrict__ m,
                             const float* __restrict__ cl, float* __restrict__ out)
{
    int tid = threadIdx.x;
    float v = ce[tid] * (1.0f / B_) + m[tid] + (ALPHA_ / B_) * cl[tid];
    __shared__ float red[512];
    red[tid] = v; __syncthreads();
    for (int st = 256; st > 0; st >>= 1) {
        if (tid < st) red[tid] += red[tid + st];
        __syncthreads();
    }
    if (tid == 0) out[0] = red[0];
}

// ---------------- host launcher ----------------
extern "C" void kernel_launch(void* const* d_in, const int* in_sizes, int n_in,
                              void* d_out, int out_size)
{
    const float* bert    = (const float*)d_in[0];
    const float* rdesc   = (const float*)d_in[1];
    const float* dense_w = (const float*)d_in[2];
    const float* dense_b = (const float*)d_in[3];
    const float* cls_w   = (const float*)d_in[4];
    const float* cls_b   = (const float*)d_in[5];
    const float* fc_w    = (const float*)d_in[6];
    const float* fc_b    = (const float*)d_in[7];
    const int*   eidx    = (const int*)d_in[8];
    const int*   lab     = (const int*)d_in[9];
    float* out = (float*)d_out;

    __nv_bfloat16 *RHb,*TOKSb,*Wd,*Wp,*rdescb,*relb,*Db;
    float *biasP,*P1,*LR,*D,*P2,*P3,*Cm,*cosm,*norms,*ce,*mm,*cl;
    cudaGetSymbolAddress((void**)&RHb,    g_RHb);
    cudaGetSymbolAddress((void**)&TOKSb,  g_TOKSb);
    cudaGetSymbolAddress((void**)&Wd,     g_Wd);
    cudaGetSymbolAddress((void**)&Wp,     g_Wp);
    cudaGetSymbolAddress((void**)&rdescb, g_rdescb);
    cudaGetSymbolAddress((void**)&relb,   g_relb);
    cudaGetSymbolAddress((void**)&Db,     g_Db);
    cudaGetSymbolAddress((void**)&biasP,  g_biasP);
    cudaGetSymbolAddress((void**)&P1,     g_P1);
    cudaGetSymbolAddress((void**)&LR,     g_LR);
    cudaGetSymbolAddress((void**)&D,      g_D);
    cudaGetSymbolAddress((void**)&P2,     g_P2);
    cudaGetSymbolAddress((void**)&P3,     g_P3);
    cudaGetSymbolAddress((void**)&Cm,     g_C);
    cudaGetSymbolAddress((void**)&cosm,   g_cos);
    cudaGetSymbolAddress((void**)&norms,  g_norms);
    cudaGetSymbolAddress((void**)&ce,     g_ce);
    cudaGetSymbolAddress((void**)&mm,     g_m);
    cudaGetSymbolAddress((void**)&cl,     g_cl);

    // prep (independent)
    gather_kernel<<<B_, 192>>>(bert, eidx, RHb, TOKSb);
    pack_kernel<<<592, 256>>>(dense_w, cls_w, fc_w, cls_b, fc_b, rdesc,
                              Wd, Wp, rdescb, biasP);

    // dense: tanh(TOKSb @ Wd^T + b) -> D fp32 + Db bf16   [2048 x 768, K=768]
    mma_nt<1><<<dim3(12, 16, 1), 256>>>(TOKSb, Wd, D, dense_b, Db,
        4*B_, H_, H_, H_, H_, H_, H_);

    // packed: RHb @ Wp^T -> P1 partials (split-K 6)   [512 x 448, K=2304]
    mma_nt<0><<<dim3(7, 4, 6), 256>>>(RHb, Wp, P1, nullptr, nullptr,
        B_, NP2_, H3_, H3_, H3_, NP2_, 384);
    reduce_packed_k<<<(B_*NP2_ + 255)/256, 256>>>(P1, biasP, LR, relb);

    // reciprocal norms (rel, rdesc, z1, z2)
    norms_kernel<<<dim3(B_, 4, 1), 256>>>(LR, rdesc, D, norms);

    // C = rel @ rdesc^T (split-K 3)   [512 x 512, K=384]
    mma_nt<0><<<dim3(8, 4, 3), 256>>>(relb, rdescb, P2, nullptr, nullptr,
        B_, B_, DS_, DS_, DS_, B_, 128);
    reduce_scale_k<<<(B_*B_)/256, 256>>>(P2, norms + 0*B_, norms + 1*B_, Cm, 3, 1.f);

    // cos = z1 @ z2^T (split-K 4)   [512 x 512, K=1536]
    mma_nt<0><<<dim3(8, 4, 4), 256>>>(Db, Db + 2*H_, P3, nullptr, nullptr,
        B_, B_, 2*H_, 4*H_, 4*H_, B_, 384);
    reduce_scale_k<<<(B_*B_)/256, 256>>>(P3, norms + 2*B_, norms + 3*B_, cosm, 4, TEMP_INV_);

    // losses
    ce_kernel<<<2, 256>>>(LR, lab, ce);
    margin_kernel<<<B_, 256>>>(Cm, lab, mm);
    cl_kernel<<<B_, 256>>>(cosm, cl);
    final_kernel<<<1, 512>>>(ce, mm, cl, out);
}

// round 8
// speedup vs baseline: 6.0676x; 1.1850x over previous
#include <cuda_runtime.h>
#include <cuda_bf16.h>
#include <math.h>
#include <stdint.h>

#define B_    512
#define S_    128
#define H_    768
#define DS_   384
#define NL_   40
#define H3_   2304
#define NP2_  448          // packed N padded to 7*64
#define TEMP_INV_ 20.0f
#define ALPHA_    0.15f
#define GAMMA_    7.5f
#define EPS_      1e-8f

// ---------------- scratch ----------------
__device__ __nv_bfloat16 g_RHb[B_ * H3_];        // tanh(concat) bf16  512x2304
__device__ __nv_bfloat16 g_TOKSb[B_ * 4 * H_];   // bf16 2048x768
__device__ __nv_bfloat16 g_Wd[H_ * H_];          // dense_w^T bf16 [768,768] (N,K)
__device__ __nv_bfloat16 g_Wp[NP2_ * H3_];       // packed W^T bf16 [448,2304]
__device__ __nv_bfloat16 g_rdescb[B_ * DS_];     // rdesc bf16
__device__ __nv_bfloat16 g_relb[B_ * DS_];       // rel bf16
__device__ __nv_bfloat16 g_Db[B_ * 4 * H_];      // tanh dense out bf16 2048x768
__device__ float g_biasP[NP2_];
__device__ float g_P1[6 * B_ * NP2_];            // packed partials
__device__ float g_LR[B_ * NP2_];
__device__ float g_D[B_ * 4 * H_];               // tanh dense out fp32
__device__ float g_P2[6 * B_ * B_];              // C partials
__device__ float g_P3[6 * B_ * B_];              // cos partials
__device__ float g_norms[4 * B_];                // recip norms: rel, rdesc, z1, z2
__device__ float g_ce[B_];
__device__ float g_m[B_];
__device__ float g_cl[B_];

__device__ __forceinline__ uint32_t smem_u32(const void* p) {
    uint32_t a;
    asm("{ .reg .u64 t; cvta.to.shared.u64 t, %1; cvt.u32.u64 %0, t; }" : "=r"(a) : "l"(p));
    return a;
}

// ================= mma.sync bf16 NT GEMM, cp.async double-buffered =================
// D[128x64 tile] = A[M,K](bf16 rm, lda) @ B[N,K]^T (bf16 rm, ldb)
// K from kBeg=z*kChunk, kChunk % 64 == 0. 8 warps: 4(M) x 2(N); warp tile 32x32.
// MODE 0: raw fp32 -> C + z*M*ldc ; MODE 1: tanh(acc+bias) -> C fp32 + Obf bf16
#define KT_ 64
#define SPAD_ 72
#define SA_ELEMS_ (128 * SPAD_)
#define SB_ELEMS_ (64 * SPAD_)
#define DYN_SMEM_BYTES_ ((2 * SA_ELEMS_ + 2 * SB_ELEMS_) * 2)

template<int MODE>
__global__ __launch_bounds__(256, 1)
void mma_nt(const __nv_bfloat16* __restrict__ A, const __nv_bfloat16* __restrict__ B,
            float* __restrict__ C, const float* __restrict__ bias,
            __nv_bfloat16* __restrict__ Obf,
            int M, int N, int K, int lda, int ldb, int ldc, int kChunk)
{
    extern __shared__ __nv_bfloat16 dyn[];
    __nv_bfloat16* sA[2] = { dyn, dyn + SA_ELEMS_ };
    __nv_bfloat16* sB[2] = { dyn + 2 * SA_ELEMS_, dyn + 2 * SA_ELEMS_ + SB_ELEMS_ };

    const int tid  = threadIdx.x;
    const int warp = tid >> 5, lane = tid & 31;
    const int wm = warp >> 1, wn = warp & 1;           // 4 x 2 warps
    const int bm = blockIdx.y * 128, bn = blockIdx.x * 64;
    const int kBeg = blockIdx.z * kChunk;

    // global load mapping (cp.async 16B each)
    const int arow = tid >> 1, ac0 = (tid & 1) * 32;   // A: 4 x 16B per thread
    const int brow = tid >> 2, bc0 = (tid & 3) * 16;   // B: 2 x 16B per thread
    const __nv_bfloat16* Ag = A + (size_t)(bm + arow) * lda + ac0;
    const __nv_bfloat16* Bg = B + (size_t)(bn + brow) * ldb + bc0;

    // ldmatrix source coords
    const int alr = lane & 15, alc = (lane >> 4) << 3;
    const int blr = lane & 7,  blc = ((lane >> 3) & 1) << 3;

    float acc[2][4][4];
#pragma unroll
    for (int mi = 0; mi < 2; mi++)
#pragma unroll
        for (int ni = 0; ni < 4; ni++)
#pragma unroll
            for (int r = 0; r < 4; r++) acc[mi][ni][r] = 0.f;

    const int nTiles = kChunk / KT_;

    // async stage loader
    auto stage = [&](int t, int s) {
        const int k0 = kBeg + t * KT_;
        uint32_t sa = smem_u32(sA[s] + arow * SPAD_ + ac0);
        const __nv_bfloat16* ag = Ag + k0;
#pragma unroll
        for (int j = 0; j < 4; j++)
            asm volatile("cp.async.cg.shared.global [%0], [%1], 16;"
                         :: "r"(sa + j * 16), "l"(ag + j * 8) : "memory");
        uint32_t sb = smem_u32(sB[s] + brow * SPAD_ + bc0);
        const __nv_bfloat16* bg = Bg + k0;
#pragma unroll
        for (int j = 0; j < 2; j++)
            asm volatile("cp.async.cg.shared.global [%0], [%1], 16;"
                         :: "r"(sb + j * 16), "l"(bg + j * 8) : "memory");
        asm volatile("cp.async.commit_group;" ::: "memory");
    };

    stage(0, 0);

    for (int t = 0; t < nTiles; t++) {
        const int s = t & 1;
        asm volatile("cp.async.wait_group 0;" ::: "memory");
        __syncthreads();
        if (t + 1 < nTiles) stage(t + 1, (t + 1) & 1);

        const __nv_bfloat16* cA = sA[s];
        const __nv_bfloat16* cB = sB[s];
#pragma unroll
        for (int ks = 0; ks < KT_ / 16; ks++) {
            const int kk = ks * 16;
            uint32_t a[2][4], b[4][2];
#pragma unroll
            for (int mi = 0; mi < 2; mi++) {
                uint32_t addr = smem_u32(cA + (wm * 32 + mi * 16 + alr) * SPAD_ + kk + alc);
                asm volatile("ldmatrix.sync.aligned.m8n8.x4.shared.b16 {%0,%1,%2,%3}, [%4];"
                             : "=r"(a[mi][0]), "=r"(a[mi][1]), "=r"(a[mi][2]), "=r"(a[mi][3])
                             : "r"(addr));
            }
#pragma unroll
            for (int ni = 0; ni < 4; ni++) {
                uint32_t addr = smem_u32(cB + (wn * 32 + ni * 8 + blr) * SPAD_ + kk + blc);
                asm volatile("ldmatrix.sync.aligned.m8n8.x2.shared.b16 {%0,%1}, [%2];"
                             : "=r"(b[ni][0]), "=r"(b[ni][1]) : "r"(addr));
            }
#pragma unroll
            for (int mi = 0; mi < 2; mi++)
#pragma unroll
                for (int ni = 0; ni < 4; ni++) {
                    asm volatile(
                        "mma.sync.aligned.m16n8k16.row.col.f32.bf16.bf16.f32 "
                        "{%0,%1,%2,%3}, {%4,%5,%6,%7}, {%8,%9}, {%0,%1,%2,%3};"
                        : "+f"(acc[mi][ni][0]), "+f"(acc[mi][ni][1]),
                          "+f"(acc[mi][ni][2]), "+f"(acc[mi][ni][3])
                        : "r"(a[mi][0]), "r"(a[mi][1]), "r"(a[mi][2]), "r"(a[mi][3]),
                          "r"(b[ni][0]), "r"(b[ni][1]));
                }
        }
    }

    const int g = lane >> 2, cpair = (lane & 3) * 2;
#pragma unroll
    for (int mi = 0; mi < 2; mi++) {
#pragma unroll
        for (int half = 0; half < 2; half++) {
            const int row = bm + wm * 32 + mi * 16 + g + half * 8;
#pragma unroll
            for (int ni = 0; ni < 4; ni++) {
                const int col = bn + wn * 32 + ni * 8 + cpair;
                float v0 = acc[mi][ni][half * 2 + 0];
                float v1 = acc[mi][ni][half * 2 + 1];
                if (MODE == 0) {
                    float* Co = C + (size_t)blockIdx.z * M * ldc + (size_t)row * ldc + col;
                    Co[0] = v0; Co[1] = v1;
                } else {
                    float t0 = tanhf(v0 + bias[col]);
                    float t1 = tanhf(v1 + bias[col + 1]);
                    float* Co = C + (size_t)row * ldc + col;
                    Co[0] = t0; Co[1] = t1;
                    *(__nv_bfloat162*)(Obf + (size_t)row * ldc + col) =
                        __floats2bfloat162_rn(t0, t1);
                }
            }
        }
    }
}

// ---------------- gather + tanh -> bf16 ----------------
__global__ void gather_kernel(const float* __restrict__ bert,
                              const int* __restrict__ eidx,
                              __nv_bfloat16* __restrict__ RHb,
                              __nv_bfloat16* __restrict__ TOKSb)
{
    int b = blockIdx.x, t = threadIdx.x;  // 0..191
    const float* base0 = bert + (size_t)b * 2 * S_ * H_;
    const float* base1 = base0 + S_ * H_;
    int i0 = eidx[b*4+0], i1 = eidx[b*4+1], i2 = eidx[b*4+2], i3 = eidx[b*4+3];
    float4 c  = ((const float4*)base0)[t];
    float4 hh = ((const float4*)(base0 + (size_t)i0*H_))[t];
    float4 tl = ((const float4*)(base0 + (size_t)i1*H_))[t];
    float4 a2 = ((const float4*)(base1 + (size_t)i2*H_))[t];
    float4 b2 = ((const float4*)(base1 + (size_t)i3*H_))[t];

    __nv_bfloat162* rh = (__nv_bfloat162*)(RHb + (size_t)b * H3_);
    __nv_bfloat162* tk = (__nv_bfloat162*)(TOKSb + (size_t)b * 4 * H_);
    rh[2*t]       = __floats2bfloat162_rn(tanhf(c.x),  tanhf(c.y));
    rh[2*t+1]     = __floats2bfloat162_rn(tanhf(c.z),  tanhf(c.w));
    rh[384+2*t]   = __floats2bfloat162_rn(tanhf(hh.x), tanhf(hh.y));
    rh[384+2*t+1] = __floats2bfloat162_rn(tanhf(hh.z), tanhf(hh.w));
    rh[768+2*t]   = __floats2bfloat162_rn(tanhf(tl.x), tanhf(tl.y));
    rh[768+2*t+1] = __floats2bfloat162_rn(tanhf(tl.z), tanhf(tl.w));
    tk[2*t]        = __floats2bfloat162_rn(hh.x, hh.y);
    tk[2*t+1]      = __floats2bfloat162_rn(hh.z, hh.w);
    tk[384+2*t]    = __floats2bfloat162_rn(tl.x, tl.y);
    tk[384+2*t+1]  = __floats2bfloat162_rn(tl.z, tl.w);
    tk[768+2*t]    = __floats2bfloat162_rn(a2.x, a2.y);
    tk[768+2*t+1]  = __floats2bfloat162_rn(a2.z, a2.w);
    tk[1152+2*t]   = __floats2bfloat162_rn(b2.x, b2.y);
    tk[1152+2*t+1] = __floats2bfloat162_rn(b2.z, b2.w);
}

// ---------------- build transposed bf16 weights ----------------
__global__ void pack_kernel(const float* __restrict__ dense_w,
                            const float* __restrict__ cls_w, const float* __restrict__ fc_w,
                            const float* __restrict__ cls_b, const float* __restrict__ fc_b,
                            const float* __restrict__ rdesc,
                            __nv_bfloat16* __restrict__ Wd, __nv_bfloat16* __restrict__ Wp,
                            __nv_bfloat16* __restrict__ rdescb, float* __restrict__ biasP)
{
    int idx = blockIdx.x * blockDim.x + threadIdx.x;
    int stride = gridDim.x * blockDim.x;
    for (int i = idx; i < H_ * H_; i += stride) {
        int n = i / H_, k = i % H_;
        Wd[i] = __float2bfloat16_rn(dense_w[(size_t)k * H_ + n]);
    }
    for (int i = idx; i < NP2_ * H3_; i += stride) {
        int n = i / H3_, k = i % H3_;
        float v = 0.f;
        if (n < NL_)            v = cls_w[(size_t)k * NL_ + n];
        else if (n < NL_ + DS_) v = fc_w[(size_t)k * DS_ + (n - NL_)];
        Wp[i] = __float2bfloat16_rn(v);
    }
    for (int i = idx; i < B_ * DS_; i += stride)
        rdescb[i] = __float2bfloat16_rn(rdesc[i]);
    if (idx < NP2_)
        biasP[idx] = (idx < NL_) ? cls_b[idx] : ((idx < NL_ + DS_) ? fc_b[idx - NL_] : 0.f);
}

// ---------------- fused post-GEMM: reduce P1 + bias + CE + all norms ----------------
// grid (B_, 4): y=0 LR-row reduce + relb + rel-norm + CE ; y=1 rdesc norm ; y=2/3 z norms
__global__ void post_kernel(const float* __restrict__ P1, const float* __restrict__ biasP,
                            const float* __restrict__ rdesc, const float* __restrict__ D,
                            const int* __restrict__ lab,
                            float* __restrict__ LR, __nv_bfloat16* __restrict__ relb,
                            float* __restrict__ norms, float* __restrict__ ce)
{
    const int b = blockIdx.x, which = blockIdx.y, tid = threadIdx.x;
    __shared__ float red[256];
    __shared__ float vals[NP2_];

    if (which == 0) {
        const int total = B_ * NP2_;
        for (int c = tid; c < NP2_; c += 256) {
            float s = biasP[c];
            int idx = b * NP2_ + c;
#pragma unroll
            for (int z = 0; z < 6; z++) s += P1[(size_t)z * total + idx];
            vals[c] = s;
            LR[idx] = s;
            if (c >= NL_ && c < NL_ + DS_)
                relb[(size_t)b * DS_ + (c - NL_)] = __float2bfloat16_rn(s);
        }
        __syncthreads();
        // rel norm over vals[40..424)
        float s = 0.f;
        for (int c = NL_ + tid; c < NL_ + DS_; c += 256) { float v = vals[c]; s += v * v; }
        red[tid] = s; __syncthreads();
        for (int st = 128; st > 0; st >>= 1) {
            if (tid < st) red[tid] += red[tid + st];
            __syncthreads();
        }
        if (tid == 0) {
            norms[b] = 1.f / fmaxf(sqrtf(red[0]), EPS_);
            // CE over vals[0..40)
            float mx = -INFINITY;
            for (int j = 0; j < NL_; j++) mx = fmaxf(mx, vals[j]);
            float se = 0.f;
            for (int j = 0; j < NL_; j++) se += expf(vals[j] - mx);
            ce[b] = mx + logf(se) - vals[lab[b]];
        }
        return;
    }

    const float* x; int len;
    if      (which == 1) { x = rdesc + (size_t)b * DS_;           len = DS_;  }
    else if (which == 2) { x = D     + (size_t)b * 4 * H_;        len = 2*H_; }
    else                 { x = D     + (size_t)b * 4 * H_ + 2*H_; len = 2*H_; }
    float s = 0.f;
    for (int i = tid; i < len; i += 256) { float v = x[i]; s += v * v; }
    red[tid] = s; __syncthreads();
    for (int st = 128; st > 0; st >>= 1) {
        if (tid < st) red[tid] += red[tid + st];
        __syncthreads();
    }
    if (tid == 0) norms[which * B_ + b] = 1.f / fmaxf(sqrtf(red[0]), EPS_);
}

// ---------------- fused margin: consume P2 partials directly ----------------
__global__ void margin_fused(const float* __restrict__ P2, const float* __restrict__ norms,
                             const int* __restrict__ lab, float* __restrict__ mout)
{
    const int b = blockIdx.x, tid = threadIdx.x;
    __shared__ float vals[B_];
    __shared__ float red[256];
    const float rsA = norms[b];
    for (int j = tid; j < B_; j += 256) {
        float s = 0.f;
        const int idx = b * B_ + j;
#pragma unroll
        for (int z = 0; z < 6; z++) s += P2[(size_t)z * B_ * B_ + idx];
        vals[j] = s * rsA * norms[B_ + j];
    }
    __syncthreads();
    const int lb = lab[b];
    float mx = -INFINITY;
    for (int j = tid; j < B_; j += 256)
        if (lab[j] != lb) mx = fmaxf(mx, vals[j]);
    red[tid] = mx; __syncthreads();
    for (int st = 128; st > 0; st >>= 1) {
        if (tid < st) red[tid] = fmaxf(red[tid], red[tid + st]);
        __syncthreads();
    }
    if (tid == 0) {
        float neg = fmaxf(red[0], 0.f);
        mout[b] = fmaxf(neg - vals[b] + GAMMA_, 0.f) * (1.0f - ALPHA_);
    }
}

// ---------------- fused cl: consume P3 partials directly ----------------
__global__ void cl_fused(const float* __restrict__ P3, const float* __restrict__ norms,
                         float* __restrict__ cl)
{
    const int b = blockIdx.x, tid = threadIdx.x;
    __shared__ float vals[B_];
    __shared__ float red[256];
    const float rsA = norms[2 * B_ + b] * TEMP_INV_;
    for (int j = tid; j < B_; j += 256) {
        float s = 0.f;
        const int idx = b * B_ + j;
#pragma unroll
        for (int z = 0; z < 6; z++) s += P3[(size_t)z * B_ * B_ + idx];
        vals[j] = s * rsA * norms[3 * B_ + j];
    }
    __syncthreads();
    float mx = -INFINITY;
    for (int j = tid; j < B_; j += 256) mx = fmaxf(mx, vals[j]);
    red[tid] = mx; __syncthreads();
    for (int st = 128; st > 0; st >>= 1) {
        if (tid < st) red[tid] = fmaxf(red[tid], red[tid + st]);
        __syncthreads();
    }
    float m = red[0]; __syncthreads();
    float s = 0.f;
    for (int j = tid; j < B_; j += 256) s += expf(vals[j] - m);
    red[tid] = s; __syncthreads();
    for (int st = 128; st > 0; st >>= 1) {
        if (tid < st) red[tid] += red[tid + st];
        __syncthreads();
    }
    if (tid == 0) cl[b] = m + logf(red[0]) - vals[b];
}

// ---------------- final combine ----------------
__global__ void final_kernel(const float* __restrict__ ce, const float* __restrict__ m,
                             const float* __restrict__ cl, float* __restrict__ out)
{
    int tid = threadIdx.x;
    float v = ce[tid] * (1.0f / B_) + m[tid] + (ALPHA_ / B_) * cl[tid];
    __shared__ float red[512];
    red[tid] = v; __syncthreads();
    for (int st = 256; st > 0; st >>= 1) {
        if (tid < st) red[tid] += red[tid + st];
        __syncthreads();
    }
    if (tid == 0) out[0] = red[0];
}

// ---------------- host launcher ----------------
extern "C" void kernel_launch(void* const* d_in, const int* in_sizes, int n_in,
                              void* d_out, int out_size)
{
    const float* bert    = (const float*)d_in[0];
    const float* rdesc   = (const float*)d_in[1];
    const float* dense_w = (const float*)d_in[2];
    const float* dense_b = (const float*)d_in[3];
    const float* cls_w   = (const float*)d_in[4];
    const float* cls_b   = (const float*)d_in[5];
    const float* fc_w    = (const float*)d_in[6];
    const float* fc_b    = (const float*)d_in[7];
    const int*   eidx    = (const int*)d_in[8];
    const int*   lab     = (const int*)d_in[9];
    float* out = (float*)d_out;

    __nv_bfloat16 *RHb,*TOKSb,*Wd,*Wp,*rdescb,*relb,*Db;
    float *biasP,*P1,*LR,*D,*P2,*P3,*norms,*ce,*mm,*cl;
    cudaGetSymbolAddress((void**)&RHb,    g_RHb);
    cudaGetSymbolAddress((void**)&TOKSb,  g_TOKSb);
    cudaGetSymbolAddress((void**)&Wd,     g_Wd);
    cudaGetSymbolAddress((void**)&Wp,     g_Wp);
    cudaGetSymbolAddress((void**)&rdescb, g_rdescb);
    cudaGetSymbolAddress((void**)&relb,   g_relb);
    cudaGetSymbolAddress((void**)&Db,     g_Db);
    cudaGetSymbolAddress((void**)&biasP,  g_biasP);
    cudaGetSymbolAddress((void**)&P1,     g_P1);
    cudaGetSymbolAddress((void**)&LR,     g_LR);
    cudaGetSymbolAddress((void**)&D,      g_D);
    cudaGetSymbolAddress((void**)&P2,     g_P2);
    cudaGetSymbolAddress((void**)&P3,     g_P3);
    cudaGetSymbolAddress((void**)&norms,  g_norms);
    cudaGetSymbolAddress((void**)&ce,     g_ce);
    cudaGetSymbolAddress((void**)&mm,     g_m);
    cudaGetSymbolAddress((void**)&cl,     g_cl);

    static int smem_set = 0;
    if (!smem_set) {
        cudaFuncSetAttribute(mma_nt<0>, cudaFuncAttributeMaxDynamicSharedMemorySize, DYN_SMEM_BYTES_);
        cudaFuncSetAttribute(mma_nt<1>, cudaFuncAttributeMaxDynamicSharedMemorySize, DYN_SMEM_BYTES_);
        smem_set = 1;
    }

    // prep (independent)
    gather_kernel<<<B_, 192>>>(bert, eidx, RHb, TOKSb);
    pack_kernel<<<592, 256>>>(dense_w, cls_w, fc_w, cls_b, fc_b, rdesc,
                              Wd, Wp, rdescb, biasP);

    // dense: tanh(TOKSb @ Wd^T + b) -> D fp32 + Db bf16   [2048 x 768, K=768]
    mma_nt<1><<<dim3(12, 16, 1), 256, DYN_SMEM_BYTES_>>>(TOKSb, Wd, D, dense_b, Db,
        4*B_, H_, H_, H_, H_, H_, H_);

    // packed: RHb @ Wp^T -> P1 (split-K 6)   [512 x 448, K=2304]
    mma_nt<0><<<dim3(7, 4, 6), 256, DYN_SMEM_BYTES_>>>(RHb, Wp, P1, nullptr, nullptr,
        B_, NP2_, H3_, H3_, H3_, NP2_, 384);

    // fused reduce + bias + CE + all norms
    post_kernel<<<dim3(B_, 4), 256>>>(P1, biasP, rdesc, D, lab, LR, relb, norms, ce);

    // C = rel @ rdesc^T (split-K 6)   [512 x 512, K=384]
    mma_nt<0><<<dim3(8, 4, 6), 256, DYN_SMEM_BYTES_>>>(relb, rdescb, P2, nullptr, nullptr,
        B_, B_, DS_, DS_, DS_, B_, 64);

    // cos = z1 @ z2^T (split-K 6)   [512 x 512, K=1536]
    mma_nt<0><<<dim3(8, 4, 6), 256, DYN_SMEM_BYTES_>>>(Db, Db + 2*H_, P3, nullptr, nullptr,
        B_, B_, 2*H_, 4*H_, 4*H_, B_, 256);

    // fused losses on partials
    margin_fused<<<B_, 256>>>(P2, norms, lab, mm);
    cl_fused<<<B_, 256>>>(P3, norms, cl);
    final_kernel<<<1, 512>>>(ce, mm, cl, out);
}